// round 17
// baseline (speedup 1.0000x reference)
#include <cuda_runtime.h>
#include <cuda_bf16.h>
#include <cstdint>

// ---------------------------------------------------------------------------
// Problem constants
// ---------------------------------------------------------------------------
#define BB        4
#define LL        5000
#define HH        256
#define WW        256
#define HW        (HH * WW)          // 65536
#define C_IN      256
#define DIM_LOI   128
#define N_PTS0    32
#define N_PTS1    8
#define DIM_FC    1024
#define N_OUT     2500
#define NROWS     (BB * LL)          // 20000
#define NPAD      20096              // 157 * 128

// ---------------------------------------------------------------------------
// Static scratch (no allocations allowed)
// ---------------------------------------------------------------------------
__device__ float g_x[(size_t)BB * HW * DIM_LOI];      // fc1 out, pixel-major
__device__ __nv_bfloat16 g_feat_h[(size_t)NPAD * DIM_FC];  // split activations
__device__ __nv_bfloat16 g_feat_l[(size_t)NPAD * DIM_FC];
__device__ __nv_bfloat16 g_h1_h[(size_t)NPAD * DIM_FC];
__device__ __nv_bfloat16 g_h1_l[(size_t)NPAD * DIM_FC];
__device__ uint32_t g_w1ph[(size_t)512 * DIM_FC];     // packed bf16 pair weights
__device__ uint32_t g_w1pl[(size_t)512 * DIM_FC];
__device__ uint32_t g_w2ph[(size_t)512 * DIM_FC];
__device__ uint32_t g_w2pl[(size_t)512 * DIM_FC];
__device__ float g_part[(size_t)NPAD * 32 * 4];       // partial logits
__device__ float g_wfc1T[(size_t)C_IN * DIM_LOI];     // fc1_w transposed [k][n]
__device__ float g_s[(size_t)NROWS * 4];              // softmax scores
__device__ int   g_key[NROWS];
__device__ int   g_order[BB * LL];
__device__ int   g_cnt[BB];

// ---------------------------------------------------------------------------
// helpers
// ---------------------------------------------------------------------------
__device__ __forceinline__ uint32_t smem_u32(const void* p) {
    uint32_t a;
    asm("{ .reg .u64 t; cvta.to.shared.u64 t, %1; cvt.u32.u64 %0, t; }" : "=r"(a) : "l"(p));
    return a;
}
__device__ __forceinline__ void ldsm4(uint32_t r[4], uint32_t addr) {
    asm volatile("ldmatrix.sync.aligned.m8n8.x4.shared.b16 {%0,%1,%2,%3}, [%4];"
                 : "=r"(r[0]), "=r"(r[1]), "=r"(r[2]), "=r"(r[3]) : "r"(addr));
}
__device__ __forceinline__ void mma_bf16(float* c, const uint32_t* a, const uint32_t* b) {
    asm volatile(
        "mma.sync.aligned.m16n8k16.row.col.f32.bf16.bf16.f32 "
        "{%0,%1,%2,%3}, {%4,%5,%6,%7}, {%8,%9}, {%0,%1,%2,%3};"
        : "+f"(c[0]), "+f"(c[1]), "+f"(c[2]), "+f"(c[3])
        : "r"(a[0]), "r"(a[1]), "r"(a[2]), "r"(a[3]), "r"(b[0]), "r"(b[1]));
}
__device__ __forceinline__ void split_bf(float v, uint32_t& h, uint32_t& l) {
    __nv_bfloat16 hb = __float2bfloat16_rn(v);
    float r = v - __bfloat162float(hb);
    __nv_bfloat16 lb = __float2bfloat16_rn(r);
    h = (uint32_t)*(uint16_t*)&hb;
    l = (uint32_t)*(uint16_t*)&lb;
}
__device__ __forceinline__ uint32_t bpack(uint32_t lo16, uint32_t hi16) {
    return lo16 | (hi16 << 16);
}
__device__ __forceinline__ void cp16(uint32_t dst, const void* src) {
    asm volatile("cp.async.cg.shared.global [%0], [%1], 16;"
                 :: "r"(dst), "l"(src) : "memory");
}
__device__ __forceinline__ void cp_commit() {
    asm volatile("cp.async.commit_group;" ::: "memory");
}
template<int N>
__device__ __forceinline__ void cp_wait() {
    asm volatile("cp.async.wait_group %0;" :: "n"(N) : "memory");
}
__device__ __forceinline__ void nbar_sync(int id) {
    asm volatile("bar.sync %0, 288;" :: "r"(id) : "memory");
}
__device__ __forceinline__ void nbar_arrive(int id) {
    asm volatile("bar.arrive %0, 288;" :: "r"(id) : "memory");
}
__device__ __forceinline__ void membar_cta() {
    asm volatile("membar.cta;" ::: "memory");
}

// ---------------------------------------------------------------------------
// bf16 smem geometry (K-chunk 16): A rows 48B stride; B packed pairs
// [k/2][n] u32, 136-u32 row stride.
// ---------------------------------------------------------------------------
#define AROWB 48
#define BSTRU 136
#define ST_AB (128 * AROWB)             // 6144 B
#define ST_BB (8 * BSTRU * 4)           // 4352 B
#define STAGE_B (2 * ST_AB + 2 * ST_BB) // 20992 B
#define NSTG  3
#define SMEM_MLP (NSTG * STAGE_B)       // 62976 B (2 CTAs: 126 KB)
#define SMEM_FC1 (2 * STAGE_B)          // 41984 B
// stage layout: Ah @0, Al @ST_AB, Bh @2*ST_AB, Bl @2*ST_AB+ST_BB

// bf16 LDSM lane offset (bytes)
__device__ __forceinline__ int ldsm_lane_off_bf(int lane) {
    int row = (((lane >> 3) & 1) << 3) + (lane & 7);
    int colB = (lane >> 4) << 4;
    return row * AROWB + colB;
}

// ---------------------------------------------------------------------------
// 3xBF16 compute on a 128x16 stage: 8 ldsm + 16 LDS + 48 MMA / warp.
// ---------------------------------------------------------------------------
__device__ __forceinline__ void compute_stage_bf(
    uint32_t AhU, uint32_t AlU,
    const uint32_t* __restrict__ Bhp, const uint32_t* __restrict__ Blp,
    int warp_n, int gr, int tg, float acc[4][4][4])
{
    uint32_t bh[4][2], bl[4][2];
#pragma unroll
    for (int nt = 0; nt < 4; nt++) {
        int c = warp_n + nt * 8 + gr;
        bh[nt][0] = Bhp[tg * BSTRU + c];
        bh[nt][1] = Bhp[(tg + 4) * BSTRU + c];
        bl[nt][0] = Blp[tg * BSTRU + c];
        bl[nt][1] = Blp[(tg + 4) * BSTRU + c];
    }
#pragma unroll
    for (int mt = 0; mt < 4; mt++) {
        uint32_t ah[4], al[4];
        const uint32_t off = (uint32_t)(mt * 16 * AROWB);
        ldsm4(ah, AhU + off);
        ldsm4(al, AlU + off);
#pragma unroll
        for (int nt = 0; nt < 4; nt++) {
            mma_bf16(acc[mt][nt], ah, bh[nt]);
            mma_bf16(acc[mt][nt], ah, bl[nt]);
            mma_bf16(acc[mt][nt], al, bh[nt]);
        }
    }
}

// ---------------------------------------------------------------------------
// Warp-specialized MLP GEMM (3xBF16):
//   288 thr = 8 consumer warps (64x32 tiles) + 1 producer warp (cp.async).
//   A: pre-split bf16 hi/lo [M][1024]; W: packed-pair u32 hi/lo [512][1024].
//   MODE=0: write split bf16 hi/lo (h1). MODE=1: fuse w3 -> partial logits.
// ---------------------------------------------------------------------------
template<int MODE>
__global__ __launch_bounds__(288, 2)
void gemm_ws(const __nv_bfloat16* __restrict__ Ah_, const __nv_bfloat16* __restrict__ Al_,
             const uint32_t* __restrict__ Wph, const uint32_t* __restrict__ Wpl,
             const float* __restrict__ bias,
             __nv_bfloat16* __restrict__ Ch, __nv_bfloat16* __restrict__ Cl,
             const float* __restrict__ w3, float* __restrict__ part)
{
    extern __shared__ __align__(16) char sm[];
    __shared__ float w3s[128 * 4];

    const int tid  = threadIdx.x;
    const int lane = tid & 31;
    const int wid  = tid >> 5;          // 0..7 consumers, 8 producer
    const int m0   = blockIdx.y * 128;
    const int n0   = blockIdx.x * 128;
    const uint32_t sb = smem_u32(sm);

    if (MODE == 1 && tid < 128)
        *(float4*)&w3s[tid * 4] = *(const float4*)(w3 + (size_t)(n0 + tid) * 4);

    if (wid == 8) {
        // ---------------- producer warp: pure cp.async ----------------
        // A: thread t -> rows 4t..4t+3; hi/lo arrays, 2x16B per row each.
        // B: thread t -> pair-row r=t>>2, seg s=t&3 (128B), 8x16B per array.
        const int t = lane;
        const __nv_bfloat16* Asrc_h = Ah_ + (size_t)(m0 + 4 * t) * 1024;
        const __nv_bfloat16* Asrc_l = Al_ + (size_t)(m0 + 4 * t) * 1024;
        const int br = t >> 2;
        const int bs = (t & 3) * 32;    // u32 offset within row
        const uint32_t* Bsrc_h = Wph + (size_t)br * 1024 + n0 + bs;
        const uint32_t* Bsrc_l = Wpl + (size_t)br * 1024 + n0 + bs;
        const uint32_t a_dst = sb + (uint32_t)(4 * t) * AROWB;
        const uint32_t b_dst = sb + 2 * ST_AB + (uint32_t)(br * BSTRU + bs) * 4;

        auto issue = [&](int ch) {
            const uint32_t st = (uint32_t)((ch % 3) * STAGE_B);
            const size_t ako = (size_t)ch * 16;
            const size_t bko = (size_t)ch * 8 * 1024;
#pragma unroll
            for (int r = 0; r < 4; r++) {
                const __nv_bfloat16* sh = Asrc_h + (size_t)r * 1024 + ako;
                const __nv_bfloat16* sl = Asrc_l + (size_t)r * 1024 + ako;
                uint32_t d = a_dst + st + (uint32_t)r * AROWB;
                cp16(d, sh);
                cp16(d + 16, sh + 8);
                cp16(d + ST_AB, sl);
                cp16(d + ST_AB + 16, sl + 8);
            }
#pragma unroll
            for (int j = 0; j < 8; j++) {
                uint32_t d = b_dst + st + (uint32_t)j * 16;
                cp16(d, Bsrc_h + bko + j * 4);
                cp16(d + ST_BB, Bsrc_l + bko + j * 4);
            }
            cp_commit();
        };

        issue(0); issue(1); issue(2);
        cp_wait<2>();
        membar_cta();
        nbar_arrive(1);                      // full[0]
        for (int ch = 0; ch < 64; ch++) {
            if (ch + 1 < 64) {               // signal full[ch+1] early
                if (ch <= 61) cp_wait<1>(); else cp_wait<0>();
                membar_cta();
                nbar_arrive(1 + ((ch + 1) % 3));
            }
            if (ch + 3 < 64) {               // backpressure + refill
                nbar_sync(4 + (ch % 3));     // consumers done with chunk ch
                issue(ch + 3);
            }
        }
        return;
    }

    // ---------------- consumer warps ----------------
    const int warp_m = (wid & 1) * 64;
    const int warp_n = (wid >> 1) * 32;
    const int gr = lane >> 2;
    const int tg = lane & 3;
    const uint32_t AU0 = sb + (uint32_t)(warp_m * AROWB + ldsm_lane_off_bf(lane));

    float acc[4][4][4];
#pragma unroll
    for (int mt = 0; mt < 4; mt++)
#pragma unroll
        for (int nt = 0; nt < 4; nt++)
#pragma unroll
            for (int r = 0; r < 4; r++) acc[mt][nt][r] = 0.f;

    for (int ch = 0; ch < 64; ch++) {
        const int p = ch % 3;
        nbar_sync(1 + p);                    // wait full[p]
        const char* st = sm + p * STAGE_B;
        compute_stage_bf(AU0 + (uint32_t)(p * STAGE_B),
                         AU0 + (uint32_t)(p * STAGE_B + ST_AB),
                         (const uint32_t*)(st + 2 * ST_AB),
                         (const uint32_t*)(st + 2 * ST_AB + ST_BB),
                         warp_n, gr, tg, acc);
        nbar_arrive(4 + p);                  // signal empty[p]
    }

    // ---- epilogue
    if (MODE == 0) {
#pragma unroll
        for (int mt = 0; mt < 4; mt++) {
            int row = m0 + warp_m + mt * 16 + gr;
#pragma unroll
            for (int nt = 0; nt < 4; nt++) {
                int col = n0 + warp_n + nt * 8 + tg * 2;
                float b0 = bias[col], b1 = bias[col + 1];
                float v00 = fmaxf(acc[mt][nt][0] + b0, 0.f);
                float v01 = fmaxf(acc[mt][nt][1] + b1, 0.f);
                float v10 = fmaxf(acc[mt][nt][2] + b0, 0.f);
                float v11 = fmaxf(acc[mt][nt][3] + b1, 0.f);
                size_t o0 = (size_t)row * 1024 + col;
                size_t o1 = (size_t)(row + 8) * 1024 + col;
                uint32_t h0, l0, h1, l1;
                split_bf(v00, h0, l0); split_bf(v01, h1, l1);
                *(uint32_t*)(Ch + o0) = bpack(h0, h1);
                *(uint32_t*)(Cl + o0) = bpack(l0, l1);
                split_bf(v10, h0, l0); split_bf(v11, h1, l1);
                *(uint32_t*)(Ch + o1) = bpack(h0, h1);
                *(uint32_t*)(Cl + o1) = bpack(l0, l1);
            }
        }
    } else {
        const int slot = blockIdx.x * 4 + (wid >> 1);   // 0..31
#pragma unroll
        for (int mt = 0; mt < 4; mt++) {
            float p0[4] = {0.f, 0.f, 0.f, 0.f};
            float p1[4] = {0.f, 0.f, 0.f, 0.f};
#pragma unroll
            for (int nt = 0; nt < 4; nt++) {
                int lc  = warp_n + nt * 8 + tg * 2;
                int col = n0 + lc;
                float b0 = bias[col], b1 = bias[col + 1];
                float v00 = fmaxf(acc[mt][nt][0] + b0, 0.f);
                float v01 = fmaxf(acc[mt][nt][1] + b1, 0.f);
                float v10 = fmaxf(acc[mt][nt][2] + b0, 0.f);
                float v11 = fmaxf(acc[mt][nt][3] + b1, 0.f);
                const float* wc0 = &w3s[lc * 4];
                const float* wc1 = &w3s[(lc + 1) * 4];
#pragma unroll
                for (int c = 0; c < 4; c++) {
                    p0[c] += v00 * wc0[c] + v01 * wc1[c];
                    p1[c] += v10 * wc0[c] + v11 * wc1[c];
                }
            }
#pragma unroll
            for (int off = 1; off < 4; off <<= 1)
#pragma unroll
                for (int c = 0; c < 4; c++) {
                    p0[c] += __shfl_xor_sync(0xffffffffu, p0[c], off);
                    p1[c] += __shfl_xor_sync(0xffffffffu, p1[c], off);
                }
            if (tg == 0) {
                int row = m0 + warp_m + mt * 16 + gr;
                *(float4*)(part + ((size_t)row * 32 + slot) * 4) =
                    make_float4(p0[0], p0[1], p0[2], p0[3]);
                *(float4*)(part + ((size_t)(row + 8) * 32 + slot) * 4) =
                    make_float4(p1[0], p1[1], p1[2], p1[3]);
            }
        }
    }
}

// ---------------------------------------------------------------------------
// fc1 GEMM (3xBF16, register loader — R15 version, unchanged)
// ---------------------------------------------------------------------------
__global__ __launch_bounds__(256, 2)
void gemm_fc1(const float* __restrict__ feature, const float* __restrict__ Wt,
              const float* __restrict__ bias, float* __restrict__ X)
{
    extern __shared__ __align__(16) char sm[];

    const int tid  = threadIdx.x;
    const int lane = tid & 31;
    const int wid  = tid >> 5;
    const int b    = blockIdx.z;
    const int m0   = blockIdx.y * 128;
    const int warp_m = (wid & 1) * 64;
    const int warp_n = (wid >> 1) * 32;
    const int gr = lane >> 2;
    const int tg = lane & 3;
    const uint32_t AU0 = smem_u32(sm)
        + (uint32_t)(warp_m * AROWB + ldsm_lane_off_bf(lane));

    const float* Ab = feature + (size_t)b * C_IN * HW;
    float* Cb = X + (size_t)b * HW * DIM_LOI;

    float acc[4][4][4];
#pragma unroll
    for (int mt = 0; mt < 4; mt++)
#pragma unroll
        for (int nt = 0; nt < 4; nt++)
#pragma unroll
            for (int r = 0; r < 4; r++) acc[mt][nt][r] = 0.f;

    const int a_m  = tid & 127;
    const int a_kh = (tid >> 7) << 3;
    const int b_k0 = (tid >> 5) << 1;
    const int b_n4 = (tid & 31) << 2;

    const float* Acol = Ab + (size_t)a_kh * HW + m0 + a_m;
    const float* Brow0 = Wt + (size_t)b_k0 * 128 + b_n4;
    const float* Brow1 = Wt + (size_t)(b_k0 + 1) * 128 + b_n4;

    float ra[8];
    float4 rb0, rb1;

    auto load_chunk = [&](int ch) {
        const size_t ko = (size_t)ch * 16;
#pragma unroll
        for (int j = 0; j < 8; j++)
            ra[j] = Acol[(ko + j) * HW];
        rb0 = *(const float4*)(Brow0 + ko * 128);
        rb1 = *(const float4*)(Brow1 + ko * 128);
    };
    auto store_chunk = [&](int p) {
        char* st = sm + p * STAGE_B;
        {
            uint32_t h[8], l[8];
#pragma unroll
            for (int j = 0; j < 8; j++) split_bf(ra[j], h[j], l[j]);
            uint4 hv = make_uint4(bpack(h[0], h[1]), bpack(h[2], h[3]),
                                  bpack(h[4], h[5]), bpack(h[6], h[7]));
            uint4 lv = make_uint4(bpack(l[0], l[1]), bpack(l[2], l[3]),
                                  bpack(l[4], l[5]), bpack(l[6], l[7]));
            int off = a_m * AROWB + a_kh * 2;
            *(uint4*)(st + off) = hv;
            *(uint4*)(st + ST_AB + off) = lv;
        }
        {
            uint32_t ha, la, hb, lb;
            uint4 hv, lv;
            split_bf(rb0.x, ha, la); split_bf(rb1.x, hb, lb);
            hv.x = bpack(ha, hb); lv.x = bpack(la, lb);
            split_bf(rb0.y, ha, la); split_bf(rb1.y, hb, lb);
            hv.y = bpack(ha, hb); lv.y = bpack(la, lb);
            split_bf(rb0.z, ha, la); split_bf(rb1.z, hb, lb);
            hv.z = bpack(ha, hb); lv.z = bpack(la, lb);
            split_bf(rb0.w, ha, la); split_bf(rb1.w, hb, lb);
            hv.w = bpack(ha, hb); lv.w = bpack(la, lb);
            int off = ((b_k0 >> 1) * BSTRU + b_n4) * 4;
            *(uint4*)(st + 2 * ST_AB + off) = hv;
            *(uint4*)(st + 2 * ST_AB + ST_BB + off) = lv;
        }
    };
    auto compute_chunk = [&](int p) {
        const char* st = sm + p * STAGE_B;
        compute_stage_bf(AU0 + (uint32_t)(p * STAGE_B),
                         AU0 + (uint32_t)(p * STAGE_B + ST_AB),
                         (const uint32_t*)(st + 2 * ST_AB),
                         (const uint32_t*)(st + 2 * ST_AB + ST_BB),
                         warp_n, gr, tg, acc);
    };

    load_chunk(0);
    store_chunk(0);
    __syncthreads();

    for (int ch = 1; ch <= 16; ch++) {
        if (ch < 16) load_chunk(ch);
        compute_chunk((ch - 1) & 1);
        if (ch < 16) store_chunk(ch & 1);
        __syncthreads();
    }

#pragma unroll
    for (int mt = 0; mt < 4; mt++) {
        int row = m0 + warp_m + mt * 16 + gr;
#pragma unroll
        for (int nt = 0; nt < 4; nt++) {
            int col = warp_n + nt * 8 + tg * 2;
            float b0 = bias[col], b1 = bias[col + 1];
            float2 v0, v1;
            v0.x = acc[mt][nt][0] + b0;
            v0.y = acc[mt][nt][1] + b1;
            v1.x = acc[mt][nt][2] + b0;
            v1.y = acc[mt][nt][3] + b1;
            *(float2*)(Cb + (size_t)row * 128 + col) = v0;
            *(float2*)(Cb + (size_t)(row + 8) * 128 + col) = v1;
        }
    }
}

// ---------------------------------------------------------------------------
// Weight prep
// ---------------------------------------------------------------------------
__global__ __launch_bounds__(256)
void transpose_fc1(const float* __restrict__ s, float* __restrict__ d)
{
    __shared__ float t[32][33];
    const int bx = blockIdx.x * 32;   // k
    const int by = blockIdx.y * 32;   // n
    const int tx = threadIdx.x, ty = threadIdx.y;
#pragma unroll
    for (int r = 0; r < 32; r += 8)
        t[ty + r][tx] = s[(size_t)(by + ty + r) * 256 + bx + tx];
    __syncthreads();
#pragma unroll
    for (int r = 0; r < 32; r += 8)
        d[(size_t)(bx + ty + r) * 128 + by + tx] = t[tx][ty + r];
}

// pack w [1024][1024] -> pair-packed u32 hi/lo [512][1024]
__global__ __launch_bounds__(256)
void pack_w(const float* __restrict__ w, uint32_t* __restrict__ ph,
            uint32_t* __restrict__ pl)
{
    int i = blockIdx.x * blockDim.x + threadIdx.x;
    if (i >= 512 * 1024) return;
    int k2 = i >> 10, n = i & 1023;
    float a = w[(size_t)(2 * k2) * 1024 + n];
    float c = w[(size_t)(2 * k2 + 1) * 1024 + n];
    uint32_t ha, la, hc, lc;
    split_bf(a, ha, la);
    split_bf(c, hc, lc);
    ph[i] = bpack(ha, hc);
    pl[i] = bpack(la, lc);
}

// ---------------------------------------------------------------------------
// Bilinear sampling + maxpool -> split bf16 feature rows.
// ---------------------------------------------------------------------------
__global__ __launch_bounds__(128)
void sample_kernel(const float* __restrict__ lines,
                   __nv_bfloat16* __restrict__ fh, __nv_bfloat16* __restrict__ fl)
{
    const int bl = blockIdx.x;
    const int b  = bl / LL;
    const int c  = threadIdx.x;

    const float* xb = g_x + (size_t)b * HW * DIM_LOI;

    float4 ln = *(const float4*)(lines + (size_t)bl * 4);
    const float x0 = ln.x, y0 = ln.y, x1 = ln.z, y1 = ln.w;

    __shared__ float stage[DIM_LOI * N_PTS1];

    float maxv = 0.f;
#pragma unroll 4
    for (int pt = 0; pt < N_PTS0; pt++) {
        float lam = (float)pt * (1.0f / 31.0f);
        float px = x0 * lam + x1 * (1.0f - lam) - 0.5f;
        float py = y0 * lam + y1 * (1.0f - lam) - 0.5f;

        float px0 = fminf(fmaxf(floorf(px), 0.f), (float)(HH - 1));
        float py0 = fminf(fmaxf(floorf(py), 0.f), (float)(WW - 1));
        float px1 = fminf(px0 + 1.f, (float)(HH - 1));
        float py1 = fminf(py0 + 1.f, (float)(WW - 1));
        int ix0 = (int)px0, iy0 = (int)py0, ix1 = (int)px1, iy1 = (int)py1;

        float w00 = (px1 - px) * (py1 - py);
        float w10 = (px - px0) * (py1 - py);
        float w01 = (px1 - px) * (py - py0);
        float w11 = (px - px0) * (py - py0);

        const float* t00 = xb + (size_t)(ix0 * WW + iy0) * DIM_LOI + c;
        const float* t10 = xb + (size_t)(ix1 * WW + iy0) * DIM_LOI + c;
        const float* t01 = xb + (size_t)(ix0 * WW + iy1) * DIM_LOI + c;
        const float* t11 = xb + (size_t)(ix1 * WW + iy1) * DIM_LOI + c;
        float v = w00 * (*t00) + w10 * (*t10) + w01 * (*t01) + w11 * (*t11);

        if ((pt & 3) == 0) maxv = v; else maxv = fmaxf(maxv, v);
        if ((pt & 3) == 3) stage[c * N_PTS1 + (pt >> 2)] = maxv;
    }
    __syncthreads();

    __nv_bfloat16* fhr = fh + (size_t)bl * DIM_FC;
    __nv_bfloat16* flr = fl + (size_t)bl * DIM_FC;
    for (int i = c; i < DIM_FC; i += DIM_LOI) {
        uint32_t h, l;
        split_bf(stage[i], h, l);
        uint16_t hu = (uint16_t)h, lu = (uint16_t)l;
        fhr[i] = *(__nv_bfloat16*)&hu;
        flr[i] = *(__nv_bfloat16*)&lu;
    }
}

// ---------------------------------------------------------------------------
// Reduce partial logits (32 slots) -> softmax + keep/key. Warp per row.
// ---------------------------------------------------------------------------
__global__ __launch_bounds__(256)
void reduce_softmax(const float* __restrict__ part, const float* __restrict__ b3)
{
    const int w    = threadIdx.x >> 5;
    const int lane = threadIdx.x & 31;
    const int row  = blockIdx.x * 8 + w;
    if (row >= NROWS) return;

    float4 p = *(const float4*)(part + ((size_t)row * 32 + lane) * 4);
    float a0 = p.x, a1 = p.y, a2 = p.z, a3 = p.w;
#pragma unroll
    for (int off = 16; off; off >>= 1) {
        a0 += __shfl_down_sync(0xffffffffu, a0, off);
        a1 += __shfl_down_sync(0xffffffffu, a1, off);
        a2 += __shfl_down_sync(0xffffffffu, a2, off);
        a3 += __shfl_down_sync(0xffffffffu, a3, off);
    }
    if (lane == 0) {
        float lg[4] = {a0 + b3[0], a1 + b3[1], a2 + b3[2], a3 + b3[3]};
        float mx = fmaxf(fmaxf(lg[0], lg[1]), fmaxf(lg[2], lg[3]));
        float e[4], sum = 0.f;
#pragma unroll
        for (int n = 0; n < 4; n++) { e[n] = __expf(lg[n] - mx); sum += e[n]; }
        float inv = 1.0f / sum;
        float s0 = e[0] * inv, s1 = e[1] * inv, s2 = e[2] * inv, s3 = e[3] * inv;
        *(float4*)(g_s + (size_t)row * 4) = make_float4(s0, s1, s2, s3);

        bool keep = ((s1 > 0.25f) || (s2 > 0.25f) || (s3 > 0.25f)) && (s0 < 0.25f);
        int am = 0; float best = s0;
        if (s1 > best) { best = s1; am = 1; }
        if (s2 > best) { best = s2; am = 2; }
        if (s3 > best) { best = s3; am = 3; }
        g_key[row] = keep ? am : -1;
    }
}

// ---------------------------------------------------------------------------
// Stable counting sort by key desc (buckets 3,2,1). One block per batch.
// ---------------------------------------------------------------------------
__global__ __launch_bounds__(1024)
void select_kernel()
{
    const int b = blockIdx.x;
    const int t = threadIdx.x;
    const int* key = g_key + b * LL;

    __shared__ int sc[3][1024];

    const int l0 = t * 5;
    const int l1 = min(l0 + 5, LL);
    int n1 = 0, n2 = 0, n3 = 0;
    for (int i = l0; i < l1; i++) {
        int k = key[i];
        n1 += (k == 1); n2 += (k == 2); n3 += (k == 3);
    }
    sc[0][t] = n1; sc[1][t] = n2; sc[2][t] = n3;
    __syncthreads();

    for (int off = 1; off < 1024; off <<= 1) {
        int v0 = (t >= off) ? sc[0][t - off] : 0;
        int v1 = (t >= off) ? sc[1][t - off] : 0;
        int v2 = (t >= off) ? sc[2][t - off] : 0;
        __syncthreads();
        sc[0][t] += v0; sc[1][t] += v1; sc[2][t] += v2;
        __syncthreads();
    }

    const int T1 = sc[0][1023], T2 = sc[1][1023], T3 = sc[2][1023];
    int p3 = sc[2][t] - n3;
    int p2 = T3 + (sc[1][t] - n2);
    int p1 = T3 + T2 + (sc[0][t] - n1);

    int* ord = g_order + b * LL;
    for (int i = l0; i < l1; i++) {
        int k = key[i];
        if (k == 3)      ord[p3++] = i;
        else if (k == 2) ord[p2++] = i;
        else if (k == 1) ord[p1++] = i;
    }
    if (t == 0) g_cnt[b] = T1 + T2 + T3;
}

// ---------------------------------------------------------------------------
// Output writer
// ---------------------------------------------------------------------------
__global__ void out_writer(const float* __restrict__ lines,
                           float* __restrict__ out, int out_size)
{
    const int gid = blockIdx.x * blockDim.x + threadIdx.x;

    if (gid < BB * N_OUT) {
        int b = gid / N_OUT, r = gid - b * N_OUT;
        int cnt = g_cnt[b];
        float4 lo = {0.f, 0.f, 0.f, 0.f};
        float4 so = {0.f, 0.f, 0.f, 0.f};
        if (cnt > 0) {
            int idx = g_order[b * LL + (r % cnt)];
            lo = *(const float4*)(lines + (size_t)(b * LL + idx) * 4);
            so = *(const float4*)(g_s + (size_t)(b * LL + idx) * 4);
        }
        *(float4*)(out + (size_t)gid * 4) = lo;
        if (out_size >= 2 * 4 * BB * N_OUT)
            *(float4*)(out + (size_t)(BB * N_OUT + gid) * 4) = so;
    }
    int g2 = gid - BB * N_OUT;
    if (g2 >= 0 && g2 < NROWS && out_size >= 8 * BB * N_OUT + 4 * NROWS) {
        *(float4*)(out + (size_t)(2 * BB * N_OUT + g2) * 4) =
            *(const float4*)(g_s + (size_t)g2 * 4);
    }
}

// ---------------------------------------------------------------------------
// Launch
// ---------------------------------------------------------------------------
extern "C" void kernel_launch(void* const* d_in, const int* in_sizes, int n_in,
                              void* d_out, int out_size)
{
    const float* feature = (const float*)d_in[0];
    const float* lines   = (const float*)d_in[1];
    const float* fc1_w   = (const float*)d_in[2];
    const float* fc1_b   = (const float*)d_in[3];
    const float* w1      = (const float*)d_in[4];
    const float* b1      = (const float*)d_in[5];
    const float* w2      = (const float*)d_in[6];
    const float* b2      = (const float*)d_in[7];
    const float* w3      = (const float*)d_in[8];
    const float* b3      = (const float*)d_in[9];
    float* out = (float*)d_out;

    float *x_p, *part_p, *wt_p;
    __nv_bfloat16 *fh_p, *fl_p, *h1h_p, *h1l_p;
    uint32_t *w1ph_p, *w1pl_p, *w2ph_p, *w2pl_p;
    cudaGetSymbolAddress((void**)&x_p,    g_x);
    cudaGetSymbolAddress((void**)&fh_p,   g_feat_h);
    cudaGetSymbolAddress((void**)&fl_p,   g_feat_l);
    cudaGetSymbolAddress((void**)&h1h_p,  g_h1_h);
    cudaGetSymbolAddress((void**)&h1l_p,  g_h1_l);
    cudaGetSymbolAddress((void**)&part_p, g_part);
    cudaGetSymbolAddress((void**)&wt_p,   g_wfc1T);
    cudaGetSymbolAddress((void**)&w1ph_p, g_w1ph);
    cudaGetSymbolAddress((void**)&w1pl_p, g_w1pl);
    cudaGetSymbolAddress((void**)&w2ph_p, g_w2ph);
    cudaGetSymbolAddress((void**)&w2pl_p, g_w2pl);

    cudaFuncSetAttribute(gemm_ws<0>, cudaFuncAttributeMaxDynamicSharedMemorySize,
                         SMEM_MLP);
    cudaFuncSetAttribute(gemm_ws<1>, cudaFuncAttributeMaxDynamicSharedMemorySize,
                         SMEM_MLP);
    cudaFuncSetAttribute(gemm_fc1, cudaFuncAttributeMaxDynamicSharedMemorySize,
                         SMEM_FC1);

    // weight prep
    transpose_fc1<<<dim3(8, 4), dim3(32, 8)>>>(fc1_w, wt_p);
    pack_w<<<2048, 256>>>(w1, w1ph_p, w1pl_p);
    pack_w<<<2048, 256>>>(w2, w2ph_p, w2pl_p);

    // fc1 on tensor cores (3xBF16)
    gemm_fc1<<<dim3(1, HW / 128, BB), 256, SMEM_FC1>>>(feature, wt_p, fc1_b, x_p);

    // bilinear sample + maxpool -> split bf16 feat
    sample_kernel<<<NROWS, DIM_LOI>>>(lines, fh_p, fl_p);

    // MLP layer 1 (warp-specialized, split output)
    gemm_ws<0><<<dim3(8, NPAD / 128), 288, SMEM_MLP>>>(
        fh_p, fl_p, w1ph_p, w1pl_p, b1, h1h_p, h1l_p, nullptr, nullptr);
    // MLP layer 2 (warp-specialized, fused w3 partial logits)
    gemm_ws<1><<<dim3(8, NPAD / 128), 288, SMEM_MLP>>>(
        h1h_p, h1l_p, w2ph_p, w2pl_p, b2, nullptr, nullptr, w3, part_p);

    // reduce partials -> softmax + keep/key
    reduce_softmax<<<(NROWS + 7) / 8, 256>>>(part_p, b3);

    // stable bucket sort per batch
    select_kernel<<<BB, 1024>>>();

    // outputs
    int tot = BB * N_OUT + NROWS;
    out_writer<<<(tot + 255) / 256, 256>>>(lines, out, out_size);
}